// round 1
// baseline (speedup 1.0000x reference)
#include <cuda_runtime.h>

// Sinkhorn OT loss: B=8, S=2048, P=1024, D=2, eps=0.01, 50 iterations.
// All potentials kept pre-scaled into log2 domain: fs = f/eps*log2(e), gs = g/eps*log2(e).
// Per half-iteration: warp-per-row two-pass LSE with register-cached arguments.

constexpr int Bn = 8;
constexpr int Sn = 2048;
constexpr int Pn = 1024;
constexpr int ITERS = 50;

constexpr float IL2     = 144.26950408889634f;   // (1/eps) * log2(e) = 100*log2e
constexpr float LOG2S   = 11.0f;                 // log2(2048)
constexpr float NEG_BIG = -1.4426950408889634e9f; // -1e9 * log2(e)

// Scratch (allocation-free rule: __device__ globals)
__device__ float4 g_xp[Bn * Sn];   // (x1, x2, -(x1^2+x2^2), 0)
__device__ float4 g_yp[Bn * Pn];   // (2*y1, 2*y2, -(y1^2+y2^2), 0)
__device__ float  g_fs[Bn * Sn];   // f * IL2 (log2-prescaled)
__device__ float  g_gs[Bn * Pn];   // g * IL2
__device__ float  g_l2b[Bn * Pn];  // log2(w) or NEG_BIG
__device__ float  g_part[Bn * Sn]; // per-row partial transport sums

__device__ __forceinline__ float ex2(float x) {
    float r; asm("ex2.approx.f32 %0, %1;" : "=f"(r) : "f"(x)); return r;
}
__device__ __forceinline__ float lg2(float x) {
    float r; asm("lg2.approx.f32 %0, %1;" : "=f"(r) : "f"(x)); return r;
}

__device__ __forceinline__ float warp_max(float m) {
    #pragma unroll
    for (int o = 16; o; o >>= 1) m = fmaxf(m, __shfl_xor_sync(0xffffffffu, m, o));
    return m;
}
__device__ __forceinline__ float warp_sum(float a) {
    #pragma unroll
    for (int o = 16; o; o >>= 1) a += __shfl_xor_sync(0xffffffffu, a, o);
    return a;
}

// ---------------------------------------------------------------- prep

__global__ void prep_x(const float* __restrict__ pred) {
    int i = blockIdx.x * blockDim.x + threadIdx.x;
    if (i < Bn * Sn) {
        float x = pred[2 * i], y = pred[2 * i + 1];
        g_xp[i] = make_float4(x, y, -(x * x + y * y), 0.f);
    }
}

__global__ void prep_y(const float* __restrict__ pos) {
    int i = blockIdx.x * blockDim.x + threadIdx.x;
    if (i < Bn * Pn) {
        float x = pos[2 * i], y = pos[2 * i + 1];
        g_yp[i] = make_float4(2.f * x, 2.f * y, -(x * x + y * y), 0.f);
        g_gs[i] = 0.f;   // g0 = 0
    }
}

__global__ void hist_kernel(const int* __restrict__ labels) {
    __shared__ int cnt[Pn];
    int b = blockIdx.x, tid = threadIdx.x;
    cnt[tid] = 0;
    __syncthreads();
    for (int s = tid; s < Sn; s += Pn)
        atomicAdd(&cnt[labels[b * Sn + s]], 1);
    __syncthreads();
    int c = cnt[tid];
    g_l2b[b * Pn + tid] = (c > 0) ? lg2((float)c * (1.f / (float)Sn)) : NEG_BIG;
}

// ---------------------------------------------------------------- sinkhorn halves

// f-update: warp per (b,s) row, LSE over P=1024 (32 entries/lane, register-cached)
__global__ void __launch_bounds__(256) f_kernel() {
    int wg   = (blockIdx.x * 256 + threadIdx.x) >> 5;   // 0..B*S-1
    int lane = threadIdx.x & 31;
    int b    = wg >> 11;                                // wg / S

    float4 X = g_xp[wg];
    const float4* __restrict__ yp = g_yp + b * Pn;
    const float*  __restrict__ gs = g_gs + b * Pn;

    float tr[32];
    float m = -3.0e38f;
    #pragma unroll
    for (int k = 0; k < 32; k++) {
        int p = lane + 32 * k;
        float4 Y = yp[p];
        float u = fmaf(X.x, Y.x, fmaf(X.y, Y.y, Y.z)); // 2*x.y - |y|^2
        float v = fminf(u + X.z, 0.f);                 // -C (clamped)
        float t = fmaf(v, IL2, gs[p]);                 // (g - C)/eps in log2
        tr[k] = t;
        m = fmaxf(m, t);
    }
    m = warp_max(m);
    float acc = 0.f;
    #pragma unroll
    for (int k = 0; k < 32; k++) acc += ex2(tr[k] - m);
    acc = warp_sum(acc);
    if (lane == 0)
        g_fs[wg] = -LOG2S - m - lg2(acc);              // log2-prescaled f
}

// g-update: warp per (b,p) column, LSE over S=2048 (64 entries/lane)
__global__ void __launch_bounds__(256) g_kernel() {
    int wg   = (blockIdx.x * 256 + threadIdx.x) >> 5;   // 0..B*P-1
    int lane = threadIdx.x & 31;
    int b    = wg >> 10;                                // wg / P

    float4 Y = g_yp[wg];
    const float4* __restrict__ xp = g_xp + b * Sn;
    const float*  __restrict__ fs = g_fs + b * Sn;

    float tr[64];
    float m = -3.0e38f;
    #pragma unroll
    for (int k = 0; k < 64; k++) {
        int s = lane + 32 * k;
        float4 X = xp[s];
        float u = fmaf(Y.x, X.x, fmaf(Y.y, X.y, X.z)); // 2*x.y - |x|^2
        float v = fminf(u + Y.z, 0.f);                 // -C
        float t = fmaf(v, IL2, fs[s]);
        tr[k] = t;
        m = fmaxf(m, t);
    }
    m = warp_max(m);
    float acc = 0.f;
    #pragma unroll
    for (int k = 0; k < 64; k++) acc += ex2(tr[k] - m);
    acc = warp_sum(acc);
    if (lane == 0)
        g_gs[wg] = g_l2b[wg] - m - lg2(acc);           // log2-prescaled g
}

// ---------------------------------------------------------------- transport distance

__global__ void __launch_bounds__(256) final_kernel() {
    int wg   = (blockIdx.x * 256 + threadIdx.x) >> 5;
    int lane = threadIdx.x & 31;
    int b    = wg >> 11;

    float4 X   = g_xp[wg];
    float  fsv = g_fs[wg];
    const float4* __restrict__ yp = g_yp + b * Pn;
    const float*  __restrict__ gs = g_gs + b * Pn;

    float acc = 0.f;
    #pragma unroll
    for (int k = 0; k < 32; k++) {
        int p = lane + 32 * k;
        float4 Y = yp[p];
        float u = fmaf(X.x, Y.x, fmaf(X.y, Y.y, Y.z));
        float v = fminf(u + X.z, 0.f);                 // -C
        float t = fmaf(v, IL2, fsv + gs[p]);           // log2(T)
        acc = fmaf(ex2(t), -v, acc);                   // T * C
    }
    acc = warp_sum(acc);
    if (lane == 0) g_part[wg] = acc;
}

__global__ void reduce_kernel(float* __restrict__ out) {
    __shared__ float sh[1024];
    int tid = threadIdx.x;
    float a = 0.f;
    for (int i = tid; i < Bn * Sn; i += 1024) a += g_part[i];
    sh[tid] = a;
    __syncthreads();
    #pragma unroll
    for (int o = 512; o; o >>= 1) {
        if (tid < o) sh[tid] += sh[tid + o];
        __syncthreads();
    }
    if (tid == 0) out[0] = sh[0] * (1.f / (float)Bn);
}

// ---------------------------------------------------------------- launch

extern "C" void kernel_launch(void* const* d_in, const int* in_sizes, int n_in,
                              void* d_out, int out_size) {
    const float* pred   = (const float*)d_in[0];
    const int*   labels = (const int*)d_in[1];
    const float* pos    = (const float*)d_in[2];
    float*       out    = (float*)d_out;

    prep_x<<<(Bn * Sn + 255) / 256, 256>>>(pred);
    prep_y<<<(Bn * Pn + 255) / 256, 256>>>(pos);
    hist_kernel<<<Bn, Pn>>>(labels);

    for (int it = 0; it < ITERS; ++it) {
        f_kernel<<<(Bn * Sn) / 8, 256>>>();   // 2048 blocks, warp/row
        g_kernel<<<(Bn * Pn) / 8, 256>>>();   // 1024 blocks, warp/col
    }

    final_kernel<<<(Bn * Sn) / 8, 256>>>();
    reduce_kernel<<<1, 1024>>>(out);
}

// round 2
// speedup vs baseline: 1.6731x; 1.6731x over previous
#include <cuda_runtime.h>

// Sinkhorn OT loss: B=8, S=2048, P=1024, D=2, eps=0.01, 50 iterations.
// Log2-domain prescaled potentials. Lane-per-row mapping with smem-broadcast
// inner operand (1 LDS.128 wavefront per 32 entries) + chunked online softmax.

constexpr int Bn = 8;
constexpr int Sn = 2048;
constexpr int Pn = 1024;
constexpr int ITERS = 50;

constexpr float IL2     = 144.26950408889634f;    // (1/eps) * log2(e)
constexpr float LOG2S   = 11.0f;                  // log2(2048)
constexpr float NEG_BIG = -1.4426950408889634e9f; // -1e9 * log2(e)

__device__ float4 g_xp[Bn * Sn];   // (x1, x2, -(x1^2+x2^2), 0)
__device__ float4 g_yp[Bn * Pn];   // (2*y1, 2*y2, -(y1^2+y2^2), 0)
__device__ float  g_fs[Bn * Sn];   // f * IL2 (log2-prescaled)
__device__ float  g_gs[Bn * Pn];   // g * IL2
__device__ float  g_l2b[Bn * Pn];  // log2(w) or NEG_BIG
__device__ float  g_part[512];     // per-block partial transport sums

__device__ __forceinline__ float ex2(float x) {
    float r; asm("ex2.approx.f32 %0, %1;" : "=f"(r) : "f"(x)); return r;
}
__device__ __forceinline__ float lg2(float x) {
    float r; asm("lg2.approx.f32 %0, %1;" : "=f"(r) : "f"(x)); return r;
}
__device__ __forceinline__ float warp_sum(float a) {
    #pragma unroll
    for (int o = 16; o; o >>= 1) a += __shfl_xor_sync(0xffffffffu, a, o);
    return a;
}

// ---------------------------------------------------------------- prep

__global__ void prep_x(const float* __restrict__ pred) {
    int i = blockIdx.x * blockDim.x + threadIdx.x;
    if (i < Bn * Sn) {
        float x = pred[2 * i], y = pred[2 * i + 1];
        g_xp[i] = make_float4(x, y, -(x * x + y * y), 0.f);
    }
}

__global__ void prep_y(const float* __restrict__ pos) {
    int i = blockIdx.x * blockDim.x + threadIdx.x;
    if (i < Bn * Pn) {
        float x = pos[2 * i], y = pos[2 * i + 1];
        g_yp[i] = make_float4(2.f * x, 2.f * y, -(x * x + y * y), 0.f);
        g_gs[i] = 0.f;   // g0 = 0
    }
}

__global__ void hist_kernel(const int* __restrict__ labels) {
    __shared__ int cnt[Pn];
    int b = blockIdx.x, tid = threadIdx.x;
    cnt[tid] = 0;
    __syncthreads();
    for (int s = tid; s < Sn; s += Pn)
        atomicAdd(&cnt[labels[b * Sn + s]], 1);
    __syncthreads();
    int c = cnt[tid];
    g_l2b[b * Pn + tid] = (c > 0) ? lg2((float)c * (1.f / (float)Sn)) : NEG_BIG;
}

// ---------------------------------------------------------------- sinkhorn halves

// f-update: block owns 32 rows (lane <-> row). 8 warps split P into 128-chunks.
// Inner operand {2y1,2y2,-|y|^2,gs} is warp-uniform -> broadcast LDS.128.
__global__ void __launch_bounds__(256) f_kernel() {
    __shared__ float4 sy[Pn];                     // 16 KB
    __shared__ float  smx[8][32], sac[8][32];

    int tid = threadIdx.x, w = tid >> 5, lane = tid & 31;
    int row0 = blockIdx.x << 5;
    int b = row0 >> 11;

    for (int i = tid; i < Pn; i += 256) {
        float4 y = g_yp[b * Pn + i];
        y.w = g_gs[b * Pn + i];
        sy[i] = y;
    }
    __syncthreads();

    int row = row0 + lane;
    float4 X = g_xp[row];
    float m = -3.0e38f, acc = 0.f;
    const float4* __restrict__ yc = sy + w * 128;

    #pragma unroll 1
    for (int c = 0; c < 16; c++) {
        float t[8];
        #pragma unroll
        for (int j = 0; j < 8; j++) {
            float4 Y = yc[c * 8 + j];
            float u = fmaf(X.x, Y.x, fmaf(X.y, Y.y, Y.z + X.z)); // -C (unclamped)
            t[j] = fmaf(fminf(u, 0.f), IL2, Y.w);
        }
        float m8 = fmaxf(fmaxf(fmaxf(t[0], t[1]), fmaxf(t[2], t[3])),
                         fmaxf(fmaxf(t[4], t[5]), fmaxf(t[6], t[7])));
        float mn = fmaxf(m, m8);
        float cs = 0.f;
        #pragma unroll
        for (int j = 0; j < 8; j++) cs += ex2(t[j] - mn);
        acc = fmaf(acc, ex2(m - mn), cs);
        m = mn;
    }

    smx[w][lane] = m; sac[w][lane] = acc;
    __syncthreads();
    if (w == 0) {
        float M = smx[0][lane];
        #pragma unroll
        for (int i = 1; i < 8; i++) M = fmaxf(M, smx[i][lane]);
        float A = 0.f;
        #pragma unroll
        for (int i = 0; i < 8; i++) A += sac[i][lane] * ex2(smx[i][lane] - M);
        g_fs[row] = -LOG2S - M - lg2(A);
    }
}

// g-update: block owns 32 cols (lane <-> col). 8 warps split S into 256-chunks.
__global__ void __launch_bounds__(256) g_kernel() {
    __shared__ float4 sx[Sn];                     // 32 KB
    __shared__ float  smx[8][32], sac[8][32];

    int tid = threadIdx.x, w = tid >> 5, lane = tid & 31;
    int col0 = blockIdx.x << 5;
    int b = col0 >> 10;

    for (int i = tid; i < Sn; i += 256) {
        float4 x = g_xp[b * Sn + i];
        x.w = g_fs[b * Sn + i];
        sx[i] = x;
    }
    __syncthreads();

    int col = col0 + lane;
    float4 Y = g_yp[col];
    float m = -3.0e38f, acc = 0.f;
    const float4* __restrict__ xc = sx + w * 256;

    #pragma unroll 1
    for (int c = 0; c < 32; c++) {
        float t[8];
        #pragma unroll
        for (int j = 0; j < 8; j++) {
            float4 Xv = xc[c * 8 + j];
            float u = fmaf(Y.x, Xv.x, fmaf(Y.y, Xv.y, Xv.z + Y.z)); // -C
            t[j] = fmaf(fminf(u, 0.f), IL2, Xv.w);
        }
        float m8 = fmaxf(fmaxf(fmaxf(t[0], t[1]), fmaxf(t[2], t[3])),
                         fmaxf(fmaxf(t[4], t[5]), fmaxf(t[6], t[7])));
        float mn = fmaxf(m, m8);
        float cs = 0.f;
        #pragma unroll
        for (int j = 0; j < 8; j++) cs += ex2(t[j] - mn);
        acc = fmaf(acc, ex2(m - mn), cs);
        m = mn;
    }

    smx[w][lane] = m; sac[w][lane] = acc;
    __syncthreads();
    if (w == 0) {
        float M = smx[0][lane];
        #pragma unroll
        for (int i = 1; i < 8; i++) M = fmaxf(M, smx[i][lane]);
        float A = 0.f;
        #pragma unroll
        for (int i = 0; i < 8; i++) A += sac[i][lane] * ex2(smx[i][lane] - M);
        g_gs[col] = g_l2b[col] - M - lg2(A);
    }
}

// ---------------------------------------------------------------- transport distance

__global__ void __launch_bounds__(256) final_kernel() {
    __shared__ float4 sy[Pn];
    __shared__ float  sred[8];

    int tid = threadIdx.x, w = tid >> 5, lane = tid & 31;
    int row0 = blockIdx.x << 5;
    int b = row0 >> 11;

    for (int i = tid; i < Pn; i += 256) {
        float4 y = g_yp[b * Pn + i];
        y.w = g_gs[b * Pn + i];
        sy[i] = y;
    }
    __syncthreads();

    int row = row0 + lane;
    float4 X = g_xp[row];
    float fsv = g_fs[row];
    const float4* __restrict__ yc = sy + w * 128;

    float acc = 0.f;
    #pragma unroll 4
    for (int k = 0; k < 128; k++) {
        float4 Y = yc[k];
        float u = fmaf(X.x, Y.x, fmaf(X.y, Y.y, Y.z + X.z));
        float v = fminf(u, 0.f);                       // -C
        float tl = fmaf(v, IL2, Y.w + fsv);            // log2(T)
        acc = fmaf(ex2(tl), -v, acc);                  // T * C
    }
    acc = warp_sum(acc);
    if (lane == 0) sred[w] = acc;
    __syncthreads();
    if (tid == 0) {
        float s = 0.f;
        #pragma unroll
        for (int i = 0; i < 8; i++) s += sred[i];
        g_part[blockIdx.x] = s;
    }
}

__global__ void reduce_kernel(float* __restrict__ out) {
    __shared__ float sh[512];
    int tid = threadIdx.x;
    sh[tid] = g_part[tid];
    __syncthreads();
    #pragma unroll
    for (int o = 256; o; o >>= 1) {
        if (tid < o) sh[tid] += sh[tid + o];
        __syncthreads();
    }
    if (tid == 0) out[0] = sh[0] * (1.f / (float)Bn);
}

// ---------------------------------------------------------------- launch

extern "C" void kernel_launch(void* const* d_in, const int* in_sizes, int n_in,
                              void* d_out, int out_size) {
    const float* pred   = (const float*)d_in[0];
    const int*   labels = (const int*)d_in[1];
    const float* pos    = (const float*)d_in[2];
    float*       out    = (float*)d_out;

    prep_x<<<(Bn * Sn + 255) / 256, 256>>>(pred);
    prep_y<<<(Bn * Pn + 255) / 256, 256>>>(pos);
    hist_kernel<<<Bn, Pn>>>(labels);

    for (int it = 0; it < ITERS; ++it) {
        f_kernel<<<(Bn * Sn) / 32, 256>>>();   // 512 blocks, 32 rows each
        g_kernel<<<(Bn * Pn) / 32, 256>>>();   // 256 blocks, 32 cols each
    }

    final_kernel<<<(Bn * Sn) / 32, 256>>>();
    reduce_kernel<<<1, 512>>>(out);
}

// round 3
// speedup vs baseline: 2.2346x; 1.3357x over previous
#include <cuda_runtime.h>

// Sinkhorn OT loss: B=8, S=2048, P=1024, D=2, eps=0.01, 50 iterations.
// Single persistent kernel: 32 CTAs per batch, per-batch sense-reversing spin
// barriers, potentials passed through L2 (STG + __ldcg). Packed f32x2 math with
// prescaled coords: t = gs - ((x1-y1)^2 + (x2-y2)^2), coords pre-multiplied by
// sqrt(100*log2e) so no per-entry scale and no clamp needed.

typedef unsigned long long ull;

constexpr int Bn = 8, Sn = 2048, Pn = 1024, ITERS = 50;
constexpr int CPB = 32;            // CTAs per batch
constexpr int GRID = Bn * CPB;     // 256 CTAs, all co-resident (occ>=2 on 148 SMs)
constexpr int NT = 256;

constexpr float IL2     = 144.26950408889634f;    // (1/eps)*log2(e)
constexpr float SQI     = 12.011224081528898f;    // sqrt(IL2)
constexpr float LOG2S   = 11.0f;                  // log2(2048)
constexpr float NEG_BIG = -1.4426950408889634e9f; // -1e9*log2(e)

__device__ float g_fs[Bn * Sn];
__device__ float g_gs[Bn * Pn];
__device__ float g_part[GRID];
__device__ unsigned g_count[Bn];            // zero-init; returns to 0 each phase
__device__ volatile unsigned g_sense[Bn];   // even #phases -> returns to init each launch

// ---------------------------------------------------------------- primitives

__device__ __forceinline__ float ex2(float x) {
    float r; asm("ex2.approx.f32 %0, %1;" : "=f"(r) : "f"(x)); return r;
}
__device__ __forceinline__ float lg2(float x) {
    float r; asm("lg2.approx.f32 %0, %1;" : "=f"(r) : "f"(x)); return r;
}
__device__ __forceinline__ ull pk(float lo, float hi) {
    ull r; asm("mov.b64 %0, {%1, %2};" : "=l"(r) : "f"(lo), "f"(hi)); return r;
}
__device__ __forceinline__ void upk(ull p, float& a, float& b) {
    asm("mov.b64 {%0, %1}, %2;" : "=f"(a), "=f"(b) : "l"(p));
}
__device__ __forceinline__ ull add2(ull a, ull b) {
    ull r; asm("add.rn.f32x2 %0, %1, %2;" : "=l"(r) : "l"(a), "l"(b)); return r;
}
__device__ __forceinline__ ull mul2(ull a, ull b) {
    ull r; asm("mul.rn.f32x2 %0, %1, %2;" : "=l"(r) : "l"(a), "l"(b)); return r;
}
__device__ __forceinline__ ull fma2(ull a, ull b, ull c) {
    ull r; asm("fma.rn.f32x2 %0, %1, %2, %3;" : "=l"(r) : "l"(a), "l"(b), "l"(c)); return r;
}
__device__ __forceinline__ float warp_sum(float a) {
    #pragma unroll
    for (int o = 16; o; o >>= 1) a += __shfl_xor_sync(0xffffffffu, a, o);
    return a;
}

// per-batch spin barrier (CPB arrivals). Deadlock-free: all CTAs co-resident.
__device__ __forceinline__ void bat_bar(int b, unsigned& lsense) {
    lsense ^= 1u;
    __threadfence();                 // each thread publishes its own STGs
    __syncthreads();
    if (threadIdx.x == 0) {
        unsigned old = atomicAdd(&g_count[b], 1);
        if (old == CPB - 1) {
            g_count[b] = 0;
            __threadfence();
            g_sense[b] = lsense;
        } else {
            while (g_sense[b] != lsense) { }
        }
        __threadfence();
    }
    __syncthreads();
}

// LSE over 256 contiguous entries starting at c0 (16 chunks x 8 packed).
// B1/B2 hold NEGATED prescaled coords; pot holds the log2-potentials.
__device__ __forceinline__ void lse_256(const float* __restrict__ B1,
                                        const float* __restrict__ B2,
                                        const float* __restrict__ pot,
                                        int c0, ull x1p, ull x2p, ull neg1,
                                        float& mo, float& Ao)
{
    float m = -3.0e38f;
    ull acc = 0ull;
    #pragma unroll 1
    for (int ch = 0; ch < 16; ch++) {
        const float* p1 = B1 + c0 + ch * 16;
        const float* p2 = B2 + c0 + ch * 16;
        const float* pp = pot + c0 + ch * 16;
        ull t[8];
        #pragma unroll
        for (int j = 0; j < 8; j++) {
            ull y1 = *(const ull*)(p1 + 2 * j);   // broadcast LDS.64
            ull y2 = *(const ull*)(p2 + 2 * j);
            ull gp = *(const ull*)(pp + 2 * j);
            ull d1 = add2(x1p, y1);               // x - y
            ull d2 = add2(x2p, y2);
            ull u  = fma2(d2, d2, mul2(d1, d1));  // C*IL2 >= 0 exactly
            t[j]   = fma2(u, neg1, gp);           // pot - C*IL2
        }
        float px[8];
        #pragma unroll
        for (int j = 0; j < 8; j++) { float a, b2; upk(t[j], a, b2); px[j] = fmaxf(a, b2); }
        float mn = fmaxf(fmaxf(fmaxf(px[0], px[1]), fmaxf(px[2], px[3])),
                         fmaxf(fmaxf(px[4], px[5]), fmaxf(px[6], px[7])));
        mn = fmaxf(m, mn);
        float r = ex2(m - mn);                    // rescale old accumulator
        ull rm = pk(-mn, -mn);
        ull e[8];
        #pragma unroll
        for (int j = 0; j < 8; j++) {
            float a, b2; upk(add2(t[j], rm), a, b2);
            e[j] = pk(ex2(a), ex2(b2));
        }
        ull s = add2(add2(add2(e[0], e[1]), add2(e[2], e[3])),
                     add2(add2(e[4], e[5]), add2(e[6], e[7])));
        acc = fma2(acc, pk(r, r), s);
        m = mn;
    }
    float a, b2; upk(acc, a, b2);
    mo = m; Ao = a + b2;
}

// ---------------------------------------------------------------- main kernel

__global__ void __launch_bounds__(NT, 2) sinkhorn_kernel(
    const float* __restrict__ pred, const int* __restrict__ labels,
    const float* __restrict__ pos)
{
    __shared__ __align__(8) float sX1[Sn], sX2[Sn], sfs[Sn];   // negated prescaled X, fs
    __shared__ __align__(8) float sY1[Pn], sY2[Pn], sgs[Pn];   // negated prescaled Y, gs
    __shared__ float smx[8][32], sac[8][32], s_l2b[32], sred[8];
    __shared__ int s_cnt[32];

    int tid = threadIdx.x, w = tid >> 5, lane = tid & 31;
    int b = blockIdx.x >> 5, cb = blockIdx.x & 31;
    int col0 = cb * 32;         // this CTA's g-columns
    int row0 = cb * 64;         // this CTA's f-rows

    // ---- prologue: stage coords (negated, prescaled), init gs=0, histogram ----
    for (int i = tid; i < Sn; i += NT) {
        float x = pred[(b * Sn + i) * 2], y = pred[(b * Sn + i) * 2 + 1];
        sX1[i] = -SQI * x; sX2[i] = -SQI * y;
    }
    for (int i = tid; i < Pn; i += NT) {
        float x = pos[(b * Pn + i) * 2], y = pos[(b * Pn + i) * 2 + 1];
        sY1[i] = -SQI * x; sY2[i] = -SQI * y;
        sgs[i] = 0.f;
    }
    if (tid < 32) s_cnt[tid] = 0;
    __syncthreads();
    for (int s = tid; s < Sn; s += NT) {
        int l = labels[b * Sn + s] - col0;
        if ((unsigned)l < 32u) atomicAdd(&s_cnt[l], 1);
    }
    __syncthreads();
    if (tid < 32) {
        int c = s_cnt[tid];
        s_l2b[tid] = (c > 0) ? lg2((float)c * (1.f / (float)Sn)) : NEG_BIG;
    }
    unsigned lsense = g_sense[b];   // stable: no CTA releases before all arrive
    __syncthreads();

    const ull neg1 = pk(-1.f, -1.f);

    // ---- 50 Sinkhorn iterations, 2 barriers each ----
    for (int it = 0; it < ITERS; ++it) {
        // f half: 64 rows, lane<->row, (w&3) quarters of P
        {
            int rl = row0 + (w >> 2) * 32 + lane;
            float x1 = -sX1[rl], x2 = -sX2[rl];
            ull x1p = pk(x1, x1), x2p = pk(x2, x2);
            float m, A;
            lse_256(sY1, sY2, sgs, (w & 3) * 256, x1p, x2p, neg1, m, A);
            smx[w][lane] = m; sac[w][lane] = A;
            __syncthreads();
            if ((w & 3) == 0) {
                float M = smx[w][lane];
                #pragma unroll
                for (int i = 1; i < 4; i++) M = fmaxf(M, smx[w + i][lane]);
                float S = 0.f;
                #pragma unroll
                for (int i = 0; i < 4; i++) S += sac[w + i][lane] * ex2(smx[w + i][lane] - M);
                g_fs[b * Sn + rl] = -LOG2S - M - lg2(S);
            }
        }
        bat_bar(b, lsense);
        for (int i = tid; i < Sn; i += NT) sfs[i] = __ldcg(&g_fs[b * Sn + i]);
        __syncthreads();

        // g half: 32 cols, lane<->col, warps split S into 8 chunks of 256
        {
            int cl = col0 + lane;
            float y1 = -sY1[cl], y2 = -sY2[cl];
            ull y1p = pk(y1, y1), y2p = pk(y2, y2);
            float m, A;
            lse_256(sX1, sX2, sfs, w * 256, y1p, y2p, neg1, m, A);
            smx[w][lane] = m; sac[w][lane] = A;
            __syncthreads();
            if (w == 0) {
                float M = smx[0][lane];
                #pragma unroll
                for (int i = 1; i < 8; i++) M = fmaxf(M, smx[i][lane]);
                float S = 0.f;
                #pragma unroll
                for (int i = 0; i < 8; i++) S += sac[i][lane] * ex2(smx[i][lane] - M);
                g_gs[b * Pn + cl] = s_l2b[lane] - M - lg2(S);
            }
        }
        bat_bar(b, lsense);
        for (int i = tid; i < Pn; i += NT) sgs[i] = __ldcg(&g_gs[b * Pn + i]);
        __syncthreads();
    }

    // ---- final transport distance: sum exp2(fs+gs-u) * u, (u = C*IL2) ----
    {
        int rl = row0 + (w >> 2) * 32 + lane;
        float x1 = -sX1[rl], x2 = -sX2[rl];
        ull x1p = pk(x1, x1), x2p = pk(x2, x2);
        float fsr = sfs[rl];
        ull fp = pk(fsr, fsr);
        int c0 = (w & 3) * 256;
        float acc = 0.f;
        #pragma unroll 1
        for (int ch = 0; ch < 16; ch++) {
            const float* p1 = sY1 + c0 + ch * 16;
            const float* p2 = sY2 + c0 + ch * 16;
            const float* pp = sgs + c0 + ch * 16;
            #pragma unroll
            for (int j = 0; j < 8; j++) {
                ull y1 = *(const ull*)(p1 + 2 * j);
                ull y2 = *(const ull*)(p2 + 2 * j);
                ull gp = *(const ull*)(pp + 2 * j);
                ull d1 = add2(x1p, y1);
                ull d2 = add2(x2p, y2);
                ull u  = fma2(d2, d2, mul2(d1, d1));
                ull tt = add2(fma2(u, neg1, gp), fp);   // log2(T)
                float ta, tb, ua, ub;
                upk(tt, ta, tb); upk(u, ua, ub);
                acc = fmaf(ex2(ta), ua, acc);
                acc = fmaf(ex2(tb), ub, acc);
            }
        }
        acc = warp_sum(acc);
        if (lane == 0) sred[w] = acc;
        __syncthreads();
        if (tid == 0) {
            float s = 0.f;
            #pragma unroll
            for (int i = 0; i < 8; i++) s += sred[i];
            g_part[blockIdx.x] = s;
        }
    }
}

// ---------------------------------------------------------------- reduce

__global__ void reduce_kernel(float* __restrict__ out) {
    __shared__ float sh[GRID];
    int tid = threadIdx.x;
    sh[tid] = g_part[tid];
    __syncthreads();
    #pragma unroll
    for (int o = GRID / 2; o; o >>= 1) {
        if (tid < o) sh[tid] += sh[tid + o];
        __syncthreads();
    }
    if (tid == 0) out[0] = sh[0] * (1.f / (IL2 * (float)Bn));
}

// ---------------------------------------------------------------- launch

extern "C" void kernel_launch(void* const* d_in, const int* in_sizes, int n_in,
                              void* d_out, int out_size) {
    const float* pred   = (const float*)d_in[0];
    const int*   labels = (const int*)d_in[1];
    const float* pos    = (const float*)d_in[2];
    float*       out    = (float*)d_out;

    sinkhorn_kernel<<<GRID, NT>>>(pred, labels, pos);
    reduce_kernel<<<1, GRID>>>(out);
}

// round 4
// speedup vs baseline: 2.5371x; 1.1353x over previous
#include <cuda_runtime.h>

// Sinkhorn OT loss: B=8, S=2048, P=1024, D=2, eps=0.01, 50 iterations.
// Persistent kernel, 32 CTAs/batch, spin barriers. Inner loop reduced to
// 2 x fma.f32x2 per packed pair via Q = pot - |y'|^2 precompute and folding
// -|x'|^2 into the post-LSE constant. f-half: 2 rows/lane (halves LDS).

typedef unsigned long long ull;

constexpr int Bn = 8, Sn = 2048, Pn = 1024, ITERS = 50;
constexpr int CPB = 32, GRID = Bn * CPB, NT = 256;

constexpr float IL2     = 144.26950408889634f;    // (1/eps)*log2(e)
constexpr float SQI     = 12.011224081528898f;    // sqrt(IL2)
constexpr float LOG2S   = 11.0f;
constexpr float NEG_BIG = -1.4426950408889634e9f;

__device__ float g_fs[Bn * Sn];
__device__ float g_gs[Bn * Pn];
__device__ float g_part[GRID];
__device__ unsigned g_cnt[Bn];
__device__ volatile unsigned g_sns[Bn];
__device__ unsigned g_gcnt;

// ---------------------------------------------------------------- primitives

__device__ __forceinline__ float ex2(float x) {
    float r; asm("ex2.approx.f32 %0, %1;" : "=f"(r) : "f"(x)); return r;
}
__device__ __forceinline__ float lg2(float x) {
    float r; asm("lg2.approx.f32 %0, %1;" : "=f"(r) : "f"(x)); return r;
}
__device__ __forceinline__ ull pk(float lo, float hi) {
    ull r; asm("mov.b64 %0, {%1, %2};" : "=l"(r) : "f"(lo), "f"(hi)); return r;
}
__device__ __forceinline__ void upk(ull p, float& a, float& b) {
    asm("mov.b64 {%0, %1}, %2;" : "=f"(a), "=f"(b) : "l"(p));
}
__device__ __forceinline__ ull add2(ull a, ull b) {
    ull r; asm("add.rn.f32x2 %0, %1, %2;" : "=l"(r) : "l"(a), "l"(b)); return r;
}
__device__ __forceinline__ ull mul2(ull a, ull b) {
    ull r; asm("mul.rn.f32x2 %0, %1, %2;" : "=l"(r) : "l"(a), "l"(b)); return r;
}
__device__ __forceinline__ ull fma2(ull a, ull b, ull c) {
    ull r; asm("fma.rn.f32x2 %0, %1, %2, %3;" : "=l"(r) : "l"(a), "l"(b), "l"(c)); return r;
}
__device__ __forceinline__ float hsum2(ull p) { float a, b; upk(p, a, b); return a + b; }
__device__ __forceinline__ float warp_sum(float a) {
    #pragma unroll
    for (int o = 16; o; o >>= 1) a += __shfl_xor_sync(0xffffffffu, a, o);
    return a;
}

// online softmax over 8 packed pairs
__device__ __forceinline__ void online8(const ull* t, float& m, ull& acc) {
    float px[8];
    #pragma unroll
    for (int j = 0; j < 8; j++) { float a, b; upk(t[j], a, b); px[j] = fmaxf(a, b); }
    float mn = fmaxf(fmaxf(fmaxf(px[0], px[1]), fmaxf(px[2], px[3])),
                     fmaxf(fmaxf(px[4], px[5]), fmaxf(px[6], px[7])));
    mn = fmaxf(m, mn);
    float r = ex2(m - mn);
    ull rm = pk(-mn, -mn);
    ull e[8];
    #pragma unroll
    for (int j = 0; j < 8; j++) {
        float a, b; upk(add2(t[j], rm), a, b);
        e[j] = pk(ex2(a), ex2(b));
    }
    ull s = add2(add2(add2(e[0], e[1]), add2(e[2], e[3])),
                 add2(add2(e[4], e[5]), add2(e[6], e[7])));
    acc = fma2(acc, pk(r, r), s);
    m = mn;
}

// per-batch spin barrier
__device__ __forceinline__ void bat_bar(int b, unsigned& ls) {
    ls ^= 1u;
    __threadfence();
    __syncthreads();
    if (threadIdx.x == 0) {
        unsigned old = atomicAdd(&g_cnt[b], 1);
        if (old == CPB - 1) {
            g_cnt[b] = 0;
            __threadfence();
            g_sns[b] = ls;
        } else {
            while (g_sns[b] != ls) { }
        }
        __threadfence();
    }
    __syncthreads();
}

// ---------------------------------------------------------------- main kernel

__global__ void __launch_bounds__(NT, 2) sinkhorn_kernel(
    const float* __restrict__ pred, const int* __restrict__ labels,
    const float* __restrict__ pos, float* __restrict__ out)
{
    __shared__ __align__(16) float4 sXC[Sn / 2];  // {x1lo,x1hi,x2lo,x2hi} * 2*SQI  (16KB)
    __shared__ __align__(16) float4 sYC[Pn / 2];  // {y1lo,y1hi,y2lo,y2hi} * SQI    (8KB)
    __shared__ __align__(8)  float  sQx[Sn];      // fs - xn  (8KB)
    __shared__ __align__(8)  float  sQy[Pn];      // gs - yn  (4KB)
    __shared__ float smx[8][64], sac[8][64];      // cross-warp LSE scratch (4KB)
    __shared__ float sxn64[64], syn32[32], s_l2b[32], sred[8];
    __shared__ int   s_cnt[32];

    int tid = threadIdx.x, w = tid >> 5, lane = tid & 31;
    int b = blockIdx.x >> 5, cb = blockIdx.x & 31;
    int row0 = cb * 64, col0 = cb * 32;

    // ---- prologue: stage prescaled coords (interleaved pairs) ----
    const float4* predv = (const float4*)pred;   // {x1lo,x2lo,x1hi,x2hi} per pair
    for (int ip = tid; ip < Sn / 2; ip += NT) {
        float4 v = predv[b * (Sn / 2) + ip];
        sXC[ip] = make_float4(2.f * SQI * v.x, 2.f * SQI * v.z,
                              2.f * SQI * v.y, 2.f * SQI * v.w);
    }
    const float4* posv = (const float4*)pos;
    for (int ip = tid; ip < Pn / 2; ip += NT) {
        float4 v = posv[b * (Pn / 2) + ip];
        sYC[ip] = make_float4(SQI * v.x, SQI * v.z, SQI * v.y, SQI * v.w);
    }
    if (tid < 32) s_cnt[tid] = 0;
    __syncthreads();

    for (int s = tid; s < Sn; s += NT) {
        int l = labels[b * Sn + s] - col0;
        if ((unsigned)l < 32u) atomicAdd(&s_cnt[l], 1);
    }
    __syncthreads();
    if (tid < 32) {
        int c = s_cnt[tid];
        s_l2b[tid] = (c > 0) ? lg2((float)c * (1.f / (float)Sn)) : NEG_BIG;
    }

    // per-lane f-row broadcasts (stored X carries factor 2*SQI)
    float X1s0, X2s0, X1s1, X2s1;
    {
        int r0 = row0 + lane, r1 = row0 + 32 + lane;
        float4 c0 = sXC[r0 >> 1], c1 = sXC[r1 >> 1];
        X1s0 = (r0 & 1) ? c0.y : c0.x;  X2s0 = (r0 & 1) ? c0.w : c0.z;
        X1s1 = (r1 & 1) ? c1.y : c1.x;  X2s1 = (r1 & 1) ? c1.w : c1.z;
    }
    float xn0 = 0.25f * (X1s0 * X1s0 + X2s0 * X2s0);   // IL2*|x|^2
    float xn1 = 0.25f * (X1s1 * X1s1 + X2s1 * X2s1);
    ull X10 = pk(X1s0, X1s0), X20 = pk(X2s0, X2s0);
    ull X11 = pk(X1s1, X1s1), X21 = pk(X2s1, X2s1);

    // per-lane g-col broadcasts (stored Y carries SQI; product X*Y = 2*IL2*x.y)
    float Y1s, Y2s;
    {
        int cl = col0 + lane;
        float4 c = sYC[cl >> 1];
        Y1s = (cl & 1) ? c.y : c.x;  Y2s = (cl & 1) ? c.w : c.z;
    }
    float ynl = Y1s * Y1s + Y2s * Y2s;                 // IL2*|y|^2
    ull Y1b = pk(Y1s, Y1s), Y2b = pk(Y2s, Y2s);

    if (w == 0) { sxn64[lane] = xn0; sxn64[32 + lane] = xn1; }
    if (tid < 32) syn32[tid] = ynl;

    // initial sQy (gs = 0): -yn
    for (int ip = tid; ip < Pn / 2; ip += NT) {
        float4 c = sYC[ip];
        sQy[2 * ip]     = -(c.x * c.x + c.z * c.z);
        sQy[2 * ip + 1] = -(c.y * c.y + c.w * c.w);
    }
    unsigned ls = g_sns[b];
    __syncthreads();

    // ---- 50 iterations ----
    for (int it = 0; it < ITERS; ++it) {
        // f half: 2 rows/lane, warp w covers col-pairs [w*64, w*64+64)
        {
            float m0 = -1e30f, m1 = -1e30f;
            ull a0 = 0ull, a1 = 0ull;
            int base = w * 64;
            #pragma unroll 1
            for (int ch = 0; ch < 8; ch++) {
                ull t0[8], t1[8];
                #pragma unroll
                for (int j = 0; j < 8; j++) {
                    float4 c = sYC[base + ch * 8 + j];
                    ull y1 = pk(c.x, c.y), y2 = pk(c.z, c.w);
                    ull q  = *(const ull*)(sQy + 2 * (base + ch * 8 + j));
                    ull w0 = fma2(X20, y2, q);
                    ull w1 = fma2(X21, y2, q);
                    t0[j] = fma2(X10, y1, w0);
                    t1[j] = fma2(X11, y1, w1);
                }
                online8(t0, m0, a0);
                online8(t1, m1, a1);
            }
            smx[w][lane]      = m0;  sac[w][lane]      = hsum2(a0);
            smx[w][lane + 32] = m1;  sac[w][lane + 32] = hsum2(a1);
        }
        __syncthreads();
        if (tid < 64) {
            float M = smx[0][tid];
            #pragma unroll
            for (int i = 1; i < 8; i++) M = fmaxf(M, smx[i][tid]);
            float A = 0.f;
            #pragma unroll
            for (int i = 0; i < 8; i++) A += sac[i][tid] * ex2(smx[i][tid] - M);
            g_fs[b * Sn + row0 + tid] = -LOG2S - M - lg2(A) + sxn64[tid];
        }
        bat_bar(b, ls);
        for (int ip = tid; ip < Sn / 2; ip += NT) {
            float4 c = sXC[ip];
            sQx[2 * ip]     = __ldcg(&g_fs[b * Sn + 2 * ip])
                              - 0.25f * (c.x * c.x + c.z * c.z);
            sQx[2 * ip + 1] = __ldcg(&g_fs[b * Sn + 2 * ip + 1])
                              - 0.25f * (c.y * c.y + c.w * c.w);
        }
        __syncthreads();

        // g half: 1 col/lane, warp w covers row-pairs [w*128, w*128+128)
        {
            float m = -1e30f;
            ull a = 0ull;
            int base = w * 128;
            #pragma unroll 1
            for (int ch = 0; ch < 16; ch++) {
                ull t[8];
                #pragma unroll
                for (int j = 0; j < 8; j++) {
                    float4 c = sXC[base + ch * 8 + j];
                    ull x1 = pk(c.x, c.y), x2 = pk(c.z, c.w);
                    ull q  = *(const ull*)(sQx + 2 * (base + ch * 8 + j));
                    t[j] = fma2(Y1b, x1, fma2(Y2b, x2, q));
                }
                online8(t, m, a);
            }
            smx[w][lane] = m;  sac[w][lane] = hsum2(a);
        }
        __syncthreads();
        if (tid < 32) {
            float M = smx[0][tid];
            #pragma unroll
            for (int i = 1; i < 8; i++) M = fmaxf(M, smx[i][tid]);
            float A = 0.f;
            #pragma unroll
            for (int i = 0; i < 8; i++) A += sac[i][tid] * ex2(smx[i][tid] - M);
            g_gs[b * Pn + col0 + tid] = s_l2b[tid] - M - lg2(A) + syn32[tid];
        }
        bat_bar(b, ls);
        for (int ip = tid; ip < Pn / 2; ip += NT) {
            float4 c = sYC[ip];
            sQy[2 * ip]     = __ldcg(&g_gs[b * Pn + 2 * ip])
                              - (c.x * c.x + c.z * c.z);
            sQy[2 * ip + 1] = __ldcg(&g_gs[b * Pn + 2 * ip + 1])
                              - (c.y * c.y + c.w * c.w);
        }
        __syncthreads();
    }

    // ---- final transport distance ----
    {
        float q0 = sQx[row0 + lane];        // fs0 - xn0 (= logT broadcast addend)
        float q1 = sQx[row0 + 32 + lane];
        int base = w * 64;
        float acc = 0.f;
        #pragma unroll 1
        for (int u = 0; u < 64; u++) {
            float4 c = sYC[base + u];
            ull y1 = pk(c.x, c.y), y2 = pk(c.z, c.w);
            ull q  = *(const ull*)(sQy + 2 * (base + u));
            ull ynp = fma2(y2, y2, mul2(y1, y1));           // IL2*|y|^2 (pair)
            ull t0 = fma2(X10, y1, fma2(X20, y2, q));
            ull t1 = fma2(X11, y1, fma2(X21, y2, q));
            float qa, qb, ya, yb, t0a, t0b, t1a, t1b;
            upk(q, qa, qb); upk(ynp, ya, yb);
            upk(t0, t0a, t0b); upk(t1, t1a, t1b);
            // C*IL2 = xn + Qy + yn - t'
            float c0a = xn0 + qa + ya - t0a;
            float c0b = xn0 + qb + yb - t0b;
            float c1a = xn1 + qa + ya - t1a;
            float c1b = xn1 + qb + yb - t1b;
            acc = fmaf(ex2(t0a + q0), c0a, acc);
            acc = fmaf(ex2(t0b + q0), c0b, acc);
            acc = fmaf(ex2(t1a + q1), c1a, acc);
            acc = fmaf(ex2(t1b + q1), c1b, acc);
        }
        acc = warp_sum(acc);
        if (lane == 0) sred[w] = acc;
    }
    __syncthreads();
    if (tid == 0) {
        float s = 0.f;
        #pragma unroll
        for (int i = 0; i < 8; i++) s += sred[i];
        g_part[blockIdx.x] = s;
    }

    // ---- grid-wide deterministic reduce (all 256 CTAs co-resident) ----
    __threadfence();
    __syncthreads();
    if (blockIdx.x == 0) {
        if (tid == 0) {
            atomicAdd(&g_gcnt, 1u);
            while (*((volatile unsigned*)&g_gcnt) < (unsigned)GRID) { }
            __threadfence();
        }
        __syncthreads();
        float v = __ldcg(&g_part[tid]);       // NT == GRID == 256
        sQy[tid] = v;                          // reuse smem as scratch
        __syncthreads();
        #pragma unroll
        for (int o = 128; o; o >>= 1) {
            if (tid < o) sQy[tid] += sQy[tid + o];
            __syncthreads();
        }
        if (tid == 0) {
            out[0] = sQy[0] * (1.f / (IL2 * (float)Bn));
            g_gcnt = 0;                        // reset for next graph replay
        }
    } else {
        if (tid == 0) atomicAdd(&g_gcnt, 1u);
    }
}

// ---------------------------------------------------------------- launch

extern "C" void kernel_launch(void* const* d_in, const int* in_sizes, int n_in,
                              void* d_out, int out_size) {
    const float* pred   = (const float*)d_in[0];
    const int*   labels = (const int*)d_in[1];
    const float* pos    = (const float*)d_in[2];
    float*       out    = (float*)d_out;

    sinkhorn_kernel<<<GRID, NT>>>(pred, labels, pos, out);
}

// round 5
// speedup vs baseline: 2.5661x; 1.0114x over previous
#include <cuda_runtime.h>

// Sinkhorn OT loss: B=8, S=2048, P=1024, D=2, eps=0.01, 50 iterations.
// Persistent kernel, 32 CTAs/batch, spin barriers. Inner loop reduced to
// 2 x fma.f32x2 per packed pair via Q = pot - |y'|^2 precompute and folding
// -|x'|^2 into the post-LSE constant. f-half: 2 rows/lane (halves LDS).

typedef unsigned long long ull;

constexpr int Bn = 8, Sn = 2048, Pn = 1024, ITERS = 50;
constexpr int CPB = 32, GRID = Bn * CPB, NT = 256;

constexpr float IL2     = 144.26950408889634f;    // (1/eps)*log2(e)
constexpr float SQI     = 12.011224081528898f;    // sqrt(IL2)
constexpr float LOG2S   = 11.0f;
constexpr float NEG_BIG = -1.4426950408889634e9f;

__device__ float g_fs[Bn * Sn];
__device__ float g_gs[Bn * Pn];
__device__ float g_part[GRID];
__device__ unsigned g_cnt[Bn];
__device__ volatile unsigned g_sns[Bn];
__device__ unsigned g_gcnt;

// ---------------------------------------------------------------- primitives

__device__ __forceinline__ float ex2(float x) {
    float r; asm("ex2.approx.f32 %0, %1;" : "=f"(r) : "f"(x)); return r;
}
__device__ __forceinline__ float lg2(float x) {
    float r; asm("lg2.approx.f32 %0, %1;" : "=f"(r) : "f"(x)); return r;
}
__device__ __forceinline__ ull pk(float lo, float hi) {
    ull r; asm("mov.b64 %0, {%1, %2};" : "=l"(r) : "f"(lo), "f"(hi)); return r;
}
__device__ __forceinline__ void upk(ull p, float& a, float& b) {
    asm("mov.b64 {%0, %1}, %2;" : "=f"(a), "=f"(b) : "l"(p));
}
__device__ __forceinline__ ull add2(ull a, ull b) {
    ull r; asm("add.rn.f32x2 %0, %1, %2;" : "=l"(r) : "l"(a), "l"(b)); return r;
}
__device__ __forceinline__ ull mul2(ull a, ull b) {
    ull r; asm("mul.rn.f32x2 %0, %1, %2;" : "=l"(r) : "l"(a), "l"(b)); return r;
}
__device__ __forceinline__ ull fma2(ull a, ull b, ull c) {
    ull r; asm("fma.rn.f32x2 %0, %1, %2, %3;" : "=l"(r) : "l"(a), "l"(b), "l"(c)); return r;
}
__device__ __forceinline__ float hsum2(ull p) { float a, b; upk(p, a, b); return a + b; }
__device__ __forceinline__ float warp_sum(float a) {
    #pragma unroll
    for (int o = 16; o; o >>= 1) a += __shfl_xor_sync(0xffffffffu, a, o);
    return a;
}

// online softmax over 8 packed pairs
__device__ __forceinline__ void online8(const ull* t, float& m, ull& acc) {
    float px[8];
    #pragma unroll
    for (int j = 0; j < 8; j++) { float a, b; upk(t[j], a, b); px[j] = fmaxf(a, b); }
    float mn = fmaxf(fmaxf(fmaxf(px[0], px[1]), fmaxf(px[2], px[3])),
                     fmaxf(fmaxf(px[4], px[5]), fmaxf(px[6], px[7])));
    mn = fmaxf(m, mn);
    float r = ex2(m - mn);
    ull rm = pk(-mn, -mn);
    ull e[8];
    #pragma unroll
    for (int j = 0; j < 8; j++) {
        float a, b; upk(add2(t[j], rm), a, b);
        e[j] = pk(ex2(a), ex2(b));
    }
    ull s = add2(add2(add2(e[0], e[1]), add2(e[2], e[3])),
                 add2(add2(e[4], e[5]), add2(e[6], e[7])));
    acc = fma2(acc, pk(r, r), s);
    m = mn;
}

// per-batch spin barrier
__device__ __forceinline__ void bat_bar(int b, unsigned& ls) {
    ls ^= 1u;
    __threadfence();
    __syncthreads();
    if (threadIdx.x == 0) {
        unsigned old = atomicAdd(&g_cnt[b], 1);
        if (old == CPB - 1) {
            g_cnt[b] = 0;
            __threadfence();
            g_sns[b] = ls;
        } else {
            while (g_sns[b] != ls) { }
        }
        __threadfence();
    }
    __syncthreads();
}

// ---------------------------------------------------------------- main kernel

__global__ void __launch_bounds__(NT, 2) sinkhorn_kernel(
    const float* __restrict__ pred, const int* __restrict__ labels,
    const float* __restrict__ pos, float* __restrict__ out)
{
    __shared__ __align__(16) float4 sXC[Sn / 2];  // {x1lo,x1hi,x2lo,x2hi} * 2*SQI  (16KB)
    __shared__ __align__(16) float4 sYC[Pn / 2];  // {y1lo,y1hi,y2lo,y2hi} * SQI    (8KB)
    __shared__ __align__(8)  float  sQx[Sn];      // fs - xn  (8KB)
    __shared__ __align__(8)  float  sQy[Pn];      // gs - yn  (4KB)
    __shared__ float smx[8][64], sac[8][64];      // cross-warp LSE scratch (4KB)
    __shared__ float sxn64[64], syn32[32], s_l2b[32], sred[8];
    __shared__ int   s_cnt[32];

    int tid = threadIdx.x, w = tid >> 5, lane = tid & 31;
    int b = blockIdx.x >> 5, cb = blockIdx.x & 31;
    int row0 = cb * 64, col0 = cb * 32;

    // ---- prologue: stage prescaled coords (interleaved pairs) ----
    const float4* predv = (const float4*)pred;   // {x1lo,x2lo,x1hi,x2hi} per pair
    for (int ip = tid; ip < Sn / 2; ip += NT) {
        float4 v = predv[b * (Sn / 2) + ip];
        sXC[ip] = make_float4(2.f * SQI * v.x, 2.f * SQI * v.z,
                              2.f * SQI * v.y, 2.f * SQI * v.w);
    }
    const float4* posv = (const float4*)pos;
    for (int ip = tid; ip < Pn / 2; ip += NT) {
        float4 v = posv[b * (Pn / 2) + ip];
        sYC[ip] = make_float4(SQI * v.x, SQI * v.z, SQI * v.y, SQI * v.w);
    }
    if (tid < 32) s_cnt[tid] = 0;
    __syncthreads();

    for (int s = tid; s < Sn; s += NT) {
        int l = labels[b * Sn + s] - col0;
        if ((unsigned)l < 32u) atomicAdd(&s_cnt[l], 1);
    }
    __syncthreads();
    if (tid < 32) {
        int c = s_cnt[tid];
        s_l2b[tid] = (c > 0) ? lg2((float)c * (1.f / (float)Sn)) : NEG_BIG;
    }

    // per-lane f-row broadcasts (stored X carries factor 2*SQI)
    float X1s0, X2s0, X1s1, X2s1;
    {
        int r0 = row0 + lane, r1 = row0 + 32 + lane;
        float4 c0 = sXC[r0 >> 1], c1 = sXC[r1 >> 1];
        X1s0 = (r0 & 1) ? c0.y : c0.x;  X2s0 = (r0 & 1) ? c0.w : c0.z;
        X1s1 = (r1 & 1) ? c1.y : c1.x;  X2s1 = (r1 & 1) ? c1.w : c1.z;
    }
    float xn0 = 0.25f * (X1s0 * X1s0 + X2s0 * X2s0);   // IL2*|x|^2
    float xn1 = 0.25f * (X1s1 * X1s1 + X2s1 * X2s1);
    ull X10 = pk(X1s0, X1s0), X20 = pk(X2s0, X2s0);
    ull X11 = pk(X1s1, X1s1), X21 = pk(X2s1, X2s1);

    // per-lane g-col broadcasts (stored Y carries SQI; product X*Y = 2*IL2*x.y)
    float Y1s, Y2s;
    {
        int cl = col0 + lane;
        float4 c = sYC[cl >> 1];
        Y1s = (cl & 1) ? c.y : c.x;  Y2s = (cl & 1) ? c.w : c.z;
    }
    float ynl = Y1s * Y1s + Y2s * Y2s;                 // IL2*|y|^2
    ull Y1b = pk(Y1s, Y1s), Y2b = pk(Y2s, Y2s);

    if (w == 0) { sxn64[lane] = xn0; sxn64[32 + lane] = xn1; }
    if (tid < 32) syn32[tid] = ynl;

    // initial sQy (gs = 0): -yn
    for (int ip = tid; ip < Pn / 2; ip += NT) {
        float4 c = sYC[ip];
        sQy[2 * ip]     = -(c.x * c.x + c.z * c.z);
        sQy[2 * ip + 1] = -(c.y * c.y + c.w * c.w);
    }
    unsigned ls = g_sns[b];
    __syncthreads();

    // ---- 50 iterations ----
    for (int it = 0; it < ITERS; ++it) {
        // f half: 2 rows/lane, warp w covers col-pairs [w*64, w*64+64)
        {
            float m0 = -1e30f, m1 = -1e30f;
            ull a0 = 0ull, a1 = 0ull;
            int base = w * 64;
            #pragma unroll 1
            for (int ch = 0; ch < 8; ch++) {
                ull t0[8], t1[8];
                #pragma unroll
                for (int j = 0; j < 8; j++) {
                    float4 c = sYC[base + ch * 8 + j];
                    ull y1 = pk(c.x, c.y), y2 = pk(c.z, c.w);
                    ull q  = *(const ull*)(sQy + 2 * (base + ch * 8 + j));
                    ull w0 = fma2(X20, y2, q);
                    ull w1 = fma2(X21, y2, q);
                    t0[j] = fma2(X10, y1, w0);
                    t1[j] = fma2(X11, y1, w1);
                }
                online8(t0, m0, a0);
                online8(t1, m1, a1);
            }
            smx[w][lane]      = m0;  sac[w][lane]      = hsum2(a0);
            smx[w][lane + 32] = m1;  sac[w][lane + 32] = hsum2(a1);
        }
        __syncthreads();
        if (tid < 64) {
            float M = smx[0][tid];
            #pragma unroll
            for (int i = 1; i < 8; i++) M = fmaxf(M, smx[i][tid]);
            float A = 0.f;
            #pragma unroll
            for (int i = 0; i < 8; i++) A += sac[i][tid] * ex2(smx[i][tid] - M);
            g_fs[b * Sn + row0 + tid] = -LOG2S - M - lg2(A) + sxn64[tid];
        }
        bat_bar(b, ls);
        for (int ip = tid; ip < Sn / 2; ip += NT) {
            float4 c = sXC[ip];
            sQx[2 * ip]     = __ldcg(&g_fs[b * Sn + 2 * ip])
                              - 0.25f * (c.x * c.x + c.z * c.z);
            sQx[2 * ip + 1] = __ldcg(&g_fs[b * Sn + 2 * ip + 1])
                              - 0.25f * (c.y * c.y + c.w * c.w);
        }
        __syncthreads();

        // g half: 1 col/lane, warp w covers row-pairs [w*128, w*128+128)
        {
            float m = -1e30f;
            ull a = 0ull;
            int base = w * 128;
            #pragma unroll 1
            for (int ch = 0; ch < 16; ch++) {
                ull t[8];
                #pragma unroll
                for (int j = 0; j < 8; j++) {
                    float4 c = sXC[base + ch * 8 + j];
                    ull x1 = pk(c.x, c.y), x2 = pk(c.z, c.w);
                    ull q  = *(const ull*)(sQx + 2 * (base + ch * 8 + j));
                    t[j] = fma2(Y1b, x1, fma2(Y2b, x2, q));
                }
                online8(t, m, a);
            }
            smx[w][lane] = m;  sac[w][lane] = hsum2(a);
        }
        __syncthreads();
        if (tid < 32) {
            float M = smx[0][tid];
            #pragma unroll
            for (int i = 1; i < 8; i++) M = fmaxf(M, smx[i][tid]);
            float A = 0.f;
            #pragma unroll
            for (int i = 0; i < 8; i++) A += sac[i][tid] * ex2(smx[i][tid] - M);
            g_gs[b * Pn + col0 + tid] = s_l2b[tid] - M - lg2(A) + syn32[tid];
        }
        bat_bar(b, ls);
        for (int ip = tid; ip < Pn / 2; ip += NT) {
            float4 c = sYC[ip];
            sQy[2 * ip]     = __ldcg(&g_gs[b * Pn + 2 * ip])
                              - (c.x * c.x + c.z * c.z);
            sQy[2 * ip + 1] = __ldcg(&g_gs[b * Pn + 2 * ip + 1])
                              - (c.y * c.y + c.w * c.w);
        }
        __syncthreads();
    }

    // ---- final transport distance ----
    {
        float q0 = sQx[row0 + lane];        // fs0 - xn0 (= logT broadcast addend)
        float q1 = sQx[row0 + 32 + lane];
        int base = w * 64;
        float acc = 0.f;
        #pragma unroll 1
        for (int u = 0; u < 64; u++) {
            float4 c = sYC[base + u];
            ull y1 = pk(c.x, c.y), y2 = pk(c.z, c.w);
            ull q  = *(const ull*)(sQy + 2 * (base + u));
            ull ynp = fma2(y2, y2, mul2(y1, y1));           // IL2*|y|^2 (pair)
            ull t0 = fma2(X10, y1, fma2(X20, y2, q));
            ull t1 = fma2(X11, y1, fma2(X21, y2, q));
            float qa, qb, ya, yb, t0a, t0b, t1a, t1b;
            upk(q, qa, qb); upk(ynp, ya, yb);
            upk(t0, t0a, t0b); upk(t1, t1a, t1b);
            // C*IL2 = xn + Qy + yn - t'
            float c0a = xn0 + qa + ya - t0a;
            float c0b = xn0 + qb + yb - t0b;
            float c1a = xn1 + qa + ya - t1a;
            float c1b = xn1 + qb + yb - t1b;
            acc = fmaf(ex2(t0a + q0), c0a, acc);
            acc = fmaf(ex2(t0b + q0), c0b, acc);
            acc = fmaf(ex2(t1a + q1), c1a, acc);
            acc = fmaf(ex2(t1b + q1), c1b, acc);
        }
        acc = warp_sum(acc);
        if (lane == 0) sred[w] = acc;
    }
    __syncthreads();
    if (tid == 0) {
        float s = 0.f;
        #pragma unroll
        for (int i = 0; i < 8; i++) s += sred[i];
        g_part[blockIdx.x] = s;
    }

    // ---- grid-wide deterministic reduce (all 256 CTAs co-resident) ----
    __threadfence();
    __syncthreads();
    if (blockIdx.x == 0) {
        if (tid == 0) {
            atomicAdd(&g_gcnt, 1u);
            while (*((volatile unsigned*)&g_gcnt) < (unsigned)GRID) { }
            __threadfence();
        }
        __syncthreads();
        float v = __ldcg(&g_part[tid]);       // NT == GRID == 256
        sQy[tid] = v;                          // reuse smem as scratch
        __syncthreads();
        #pragma unroll
        for (int o = 128; o; o >>= 1) {
            if (tid < o) sQy[tid] += sQy[tid + o];
            __syncthreads();
        }
        if (tid == 0) {
            out[0] = sQy[0] * (1.f / (IL2 * (float)Bn));
            g_gcnt = 0;                        // reset for next graph replay
        }
    } else {
        if (tid == 0) atomicAdd(&g_gcnt, 1u);
    }
}

// ---------------------------------------------------------------- launch

extern "C" void kernel_launch(void* const* d_in, const int* in_sizes, int n_in,
                              void* d_out, int out_size) {
    const float* pred   = (const float*)d_in[0];
    const int*   labels = (const int*)d_in[1];
    const float* pos    = (const float*)d_in[2];
    float*       out    = (float*)d_out;

    sinkhorn_kernel<<<GRID, NT>>>(pred, labels, pos, out);
}